// round 2
// baseline (speedup 1.0000x reference)
#include <cuda_runtime.h>
#include <cstdio>

#define BB   2
#define TT   2048
#define DD   4096
#define HH   32
#define GG   8
#define DH   128
#define GRP  4
#define KVD  (GG*DH)     /* 1024 */
#define MTOT (BB*TT)     /* 4096 */

// Scratch intermediates (device globals — no runtime allocation allowed)
__device__ float g_Q[(size_t)MTOT * DD];   // 64 MB
__device__ float g_K[(size_t)MTOT * KVD];  // 16 MB
__device__ float g_V[(size_t)MTOT * KVD];  // 16 MB
__device__ float g_Y[(size_t)MTOT * DD];   // 64 MB

// ---------------------------------------------------------------------------
// C[M,N] = A[M,K] @ W[N,K]^T + bias[N]   (both row-major, inner dim K = "NT")
// 128x128x16 tile, 256 threads, 8x8 microtile per thread.
// ---------------------------------------------------------------------------
__global__ __launch_bounds__(256, 2) void gemm_nt_bias(
    const float* __restrict__ A, const float* __restrict__ W,
    const float* __restrict__ bias, float* __restrict__ C,
    int M, int N, int K)
{
    __shared__ float As[16][128];
    __shared__ float Ws[16][128];

    const int tid  = threadIdx.x;
    const int ty   = tid >> 4;        // 0..15
    const int tx   = tid & 15;        // 0..15
    const int brow = blockIdx.y << 7;
    const int bcol = blockIdx.x << 7;

    float acc[8][8];
    #pragma unroll
    for (int i = 0; i < 8; i++)
        #pragma unroll
        for (int j = 0; j < 8; j++) acc[i][j] = 0.f;

    const int ar = tid >> 2;          // 0..63 (two passes cover 128 rows)
    const int ac = (tid & 3) << 2;    // 0,4,8,12

    for (int k0 = 0; k0 < K; k0 += 16) {
        #pragma unroll
        for (int p = 0; p < 2; p++) {
            int r = ar + p * 64;
            float4 va = *(const float4*)&A[(size_t)(brow + r) * K + k0 + ac];
            As[ac + 0][r] = va.x; As[ac + 1][r] = va.y;
            As[ac + 2][r] = va.z; As[ac + 3][r] = va.w;
            float4 vw = *(const float4*)&W[(size_t)(bcol + r) * K + k0 + ac];
            Ws[ac + 0][r] = vw.x; Ws[ac + 1][r] = vw.y;
            Ws[ac + 2][r] = vw.z; Ws[ac + 3][r] = vw.w;
        }
        __syncthreads();

        #pragma unroll
        for (int k = 0; k < 16; k++) {
            float a[8], w[8];
            *(float4*)&a[0] = *(const float4*)&As[k][ty * 8];
            *(float4*)&a[4] = *(const float4*)&As[k][ty * 8 + 4];
            *(float4*)&w[0] = *(const float4*)&Ws[k][tx * 8];
            *(float4*)&w[4] = *(const float4*)&Ws[k][tx * 8 + 4];
            #pragma unroll
            for (int i = 0; i < 8; i++)
                #pragma unroll
                for (int j = 0; j < 8; j++)
                    acc[i][j] += a[i] * w[j];
        }
        __syncthreads();
    }

    #pragma unroll
    for (int i = 0; i < 8; i++) {
        size_t row = (size_t)(brow + ty * 8 + i);
        #pragma unroll
        for (int j = 0; j < 8; j += 4) {
            float4 v;
            v.x = acc[i][j + 0] + bias[bcol + tx * 8 + j + 0];
            v.y = acc[i][j + 1] + bias[bcol + tx * 8 + j + 1];
            v.z = acc[i][j + 2] + bias[bcol + tx * 8 + j + 2];
            v.w = acc[i][j + 3] + bias[bcol + tx * 8 + j + 3];
            *(float4*)&C[row * N + bcol + tx * 8 + j] = v;
        }
    }
}

// ---------------------------------------------------------------------------
// Causal GQA flash attention, fp32.
// Block = 64 query rows of one head; loops over 64-key tiles with online
// softmax. 256 threads: (ty,tx) 16x16 grid; S microtile 4x4, O microtile 4x8.
// Shared K/V buffer (loaded sequentially) keeps smem at 85 KB -> 2 CTAs/SM.
// grid = (T/64, B*H)
// ---------------------------------------------------------------------------
#define ATTN_LD 132   // 128 + 4 pad (bank-conflict break)
#define ATTN_SS 68    // 64 + 4 pad
#define ATTN_SMEM ((2*64*ATTN_LD + 64*ATTN_SS) * (int)sizeof(float))

__global__ __launch_bounds__(256, 2) void attn_kernel(
    const float* __restrict__ Q, const float* __restrict__ K,
    const float* __restrict__ V, float* __restrict__ Y)
{
    extern __shared__ float sm[];
    float* Qs  = sm;                      // 64 x ATTN_LD
    float* KVs = sm + 64 * ATTN_LD;       // 64 x ATTN_LD (K then V)
    float* Ps  = sm + 2 * 64 * ATTN_LD;   // 64 x ATTN_SS

    const int tid = threadIdx.x;
    const int ty  = tid >> 4;             // 0..15 -> q rows ty*4..+3
    const int tx  = tid & 15;             // 0..15 -> k cols tx*4..+3 / o cols tx+j*16
    const int qt  = blockIdx.x;
    const int bh  = blockIdx.y;
    const int b   = bh >> 5;              // / 32 heads
    const int h   = bh & 31;
    const int g   = h >> 2;               // / GROUP

    const float* Qbase = Q + ((size_t)(b * TT + qt * 64)) * DD + h * DH;
    const float* Kbase = K + (size_t)b * TT * KVD + g * DH;
    const float* Vbase = V + (size_t)b * TT * KVD + g * DH;

    // load Q tile: 64 rows x 128 cols
    for (int i = tid; i < 64 * 32; i += 256) {
        int r = i >> 5, c = (i & 31) << 2;
        *(float4*)&Qs[r * ATTN_LD + c] = *(const float4*)&Qbase[(size_t)r * DD + c];
    }

    float m_i[4], l_i[4], o[4][8];
    #pragma unroll
    for (int i = 0; i < 4; i++) {
        m_i[i] = -1e30f; l_i[i] = 0.f;
        #pragma unroll
        for (int j = 0; j < 8; j++) o[i][j] = 0.f;
    }
    __syncthreads();

    const float scale = 0.08838834764831843f;  // 1/sqrt(128)

    for (int kt = 0; kt <= qt; kt++) {
        // ---- load K tile ----
        for (int i = tid; i < 64 * 32; i += 256) {
            int r = i >> 5, c = (i & 31) << 2;
            *(float4*)&KVs[r * ATTN_LD + c] =
                *(const float4*)&Kbase[(size_t)(kt * 64 + r) * KVD + c];
        }
        __syncthreads();

        // ---- S = Q K^T (4x4 microtile, float4 over k) ----
        float s[4][4];
        #pragma unroll
        for (int i = 0; i < 4; i++)
            #pragma unroll
            for (int j = 0; j < 4; j++) s[i][j] = 0.f;

        #pragma unroll 8
        for (int k = 0; k < DH; k += 4) {
            float4 qv[4], kv[4];
            #pragma unroll
            for (int i = 0; i < 4; i++)
                qv[i] = *(const float4*)&Qs[(ty * 4 + i) * ATTN_LD + k];
            #pragma unroll
            for (int j = 0; j < 4; j++)
                kv[j] = *(const float4*)&KVs[(tx * 4 + j) * ATTN_LD + k];
            #pragma unroll
            for (int i = 0; i < 4; i++)
                #pragma unroll
                for (int j = 0; j < 4; j++) {
                    s[i][j] += qv[i].x * kv[j].x;
                    s[i][j] += qv[i].y * kv[j].y;
                    s[i][j] += qv[i].z * kv[j].z;
                    s[i][j] += qv[i].w * kv[j].w;
                }
        }

        // ---- online softmax update ----
        const bool diag = (kt == qt);
        #pragma unroll
        for (int i = 0; i < 4; i++) {
            #pragma unroll
            for (int j = 0; j < 4; j++) {
                s[i][j] *= scale;
                if (diag && (tx * 4 + j) > (ty * 4 + i)) s[i][j] = -1e30f;
            }
            float v = fmaxf(fmaxf(s[i][0], s[i][1]), fmaxf(s[i][2], s[i][3]));
            #pragma unroll
            for (int off = 8; off; off >>= 1)
                v = fmaxf(v, __shfl_xor_sync(0xffffffffu, v, off));
            float mnew = fmaxf(m_i[i], v);
            float corr = __expf(m_i[i] - mnew);
            float ss = 0.f;
            #pragma unroll
            for (int j = 0; j < 4; j++) {
                s[i][j] = __expf(s[i][j] - mnew);
                ss += s[i][j];
            }
            #pragma unroll
            for (int off = 8; off; off >>= 1)
                ss += __shfl_xor_sync(0xffffffffu, ss, off);
            l_i[i] = l_i[i] * corr + ss;
            m_i[i] = mnew;
            #pragma unroll
            for (int j = 0; j < 8; j++) o[i][j] *= corr;
            #pragma unroll
            for (int j = 0; j < 4; j++)
                Ps[(ty * 4 + i) * ATTN_SS + tx * 4 + j] = s[i][j];
        }
        __syncthreads();   // K reads + P writes done

        // ---- load V tile (reuses K buffer) ----
        for (int i = tid; i < 64 * 32; i += 256) {
            int r = i >> 5, c = (i & 31) << 2;
            *(float4*)&KVs[r * ATTN_LD + c] =
                *(const float4*)&Vbase[(size_t)(kt * 64 + r) * KVD + c];
        }
        __syncthreads();

        // ---- O += P V ----
        #pragma unroll 4
        for (int s2 = 0; s2 < 64; s2++) {
            float pv[4];
            #pragma unroll
            for (int i = 0; i < 4; i++) pv[i] = Ps[(ty * 4 + i) * ATTN_SS + s2];
            float vv[8];
            #pragma unroll
            for (int j = 0; j < 8; j++) vv[j] = KVs[s2 * ATTN_LD + tx + j * 16];
            #pragma unroll
            for (int i = 0; i < 4; i++)
                #pragma unroll
                for (int j = 0; j < 8; j++) o[i][j] += pv[i] * vv[j];
        }
        __syncthreads();   // before next tile overwrites KVs/Ps
    }

    // ---- epilogue: normalize and write back (head-concatenated layout) ----
    #pragma unroll
    for (int i = 0; i < 4; i++) {
        float inv = 1.f / l_i[i];
        size_t row = (size_t)(b * TT + qt * 64 + ty * 4 + i);
        #pragma unroll
        for (int j = 0; j < 8; j++)
            Y[row * DD + h * DH + tx + j * 16] = o[i][j] * inv;
    }
}

// ---------------------------------------------------------------------------
extern "C" void kernel_launch(void* const* d_in, const int* in_sizes, int n_in,
                              void* d_out, int out_size)
{
    (void)in_sizes; (void)n_in; (void)out_size;
    const float* X  = (const float*)d_in[0];
    const float* Wq = (const float*)d_in[1];
    const float* bq = (const float*)d_in[2];
    const float* Wk = (const float*)d_in[3];
    const float* bk = (const float*)d_in[4];
    const float* Wv = (const float*)d_in[5];
    const float* bv = (const float*)d_in[6];
    const float* Wo = (const float*)d_in[7];
    const float* bo = (const float*)d_in[8];
    float* out = (float*)d_out;

    float *Qp, *Kp, *Vp, *Yp;
    cudaGetSymbolAddress((void**)&Qp, g_Q);
    cudaGetSymbolAddress((void**)&Kp, g_K);
    cudaGetSymbolAddress((void**)&Vp, g_V);
    cudaGetSymbolAddress((void**)&Yp, g_Y);

    cudaFuncSetAttribute(attn_kernel,
                         cudaFuncAttributeMaxDynamicSharedMemorySize, ATTN_SMEM);

    dim3 blk(256);
    // Q/K/V projections
    gemm_nt_bias<<<dim3(DD / 128, MTOT / 128), blk>>>(X, Wq, bq, Qp, MTOT, DD, DD);
    gemm_nt_bias<<<dim3(KVD / 128, MTOT / 128), blk>>>(X, Wk, bk, Kp, MTOT, KVD, DD);
    gemm_nt_bias<<<dim3(KVD / 128, MTOT / 128), blk>>>(X, Wv, bv, Vp, MTOT, KVD, DD);
    // causal GQA attention
    attn_kernel<<<dim3(TT / 64, BB * HH), blk, ATTN_SMEM>>>(Qp, Kp, Vp, Yp);
    // output projection
    gemm_nt_bias<<<dim3(DD / 128, MTOT / 128), blk>>>(Yp, Wo, bo, out, MTOT, DD, DD);
}

// round 4
// speedup vs baseline: 1.8147x; 1.8147x over previous
#include <cuda_runtime.h>
#include <cuda_bf16.h>
#include <cstdint>

#define BB   2
#define TT   2048
#define DD   4096
#define HH   32
#define GG   8
#define DH   128
#define KVD  (GG*DH)     /* 1024 */
#define MTOT (BB*TT)     /* 4096 */

// fp32 intermediates
__device__ float g_Q[(size_t)MTOT * DD];
__device__ float g_K[(size_t)MTOT * KVD];
__device__ float g_V[(size_t)MTOT * KVD];
__device__ float g_Y[(size_t)MTOT * DD];

// bf16 hi/lo split operands
__device__ __nv_bfloat16 g_X_hi[(size_t)MTOT * DD], g_X_lo[(size_t)MTOT * DD];
__device__ __nv_bfloat16 g_Wq_hi[(size_t)DD * DD],  g_Wq_lo[(size_t)DD * DD];
__device__ __nv_bfloat16 g_Wk_hi[(size_t)KVD * DD], g_Wk_lo[(size_t)KVD * DD];
__device__ __nv_bfloat16 g_Wv_hi[(size_t)KVD * DD], g_Wv_lo[(size_t)KVD * DD];
__device__ __nv_bfloat16 g_Wo_hi[(size_t)DD * DD],  g_Wo_lo[(size_t)DD * DD];
__device__ __nv_bfloat16 g_Y_hi[(size_t)MTOT * DD], g_Y_lo[(size_t)MTOT * DD];

// ---------------------------------------------------------------------------
// base-PTX helpers (compute_103-safe: no "a"-only instructions)
// ---------------------------------------------------------------------------
__device__ __forceinline__ uint32_t smem_u32(const void* p) {
    uint32_t a;
    asm("{ .reg .u64 t; cvta.to.shared.u64 t, %1; cvt.u32.u64 %0, t; }"
        : "=r"(a) : "l"(p));
    return a;
}
__device__ __forceinline__ void ldsm4(uint32_t& r0, uint32_t& r1, uint32_t& r2,
                                      uint32_t& r3, uint32_t addr) {
    asm volatile("ldmatrix.sync.aligned.m8n8.x4.shared.b16 {%0,%1,%2,%3}, [%4];"
                 : "=r"(r0), "=r"(r1), "=r"(r2), "=r"(r3) : "r"(addr));
}
__device__ __forceinline__ void mma16816(float* c, const uint32_t* a,
                                         uint32_t b0, uint32_t b1) {
    asm volatile(
        "mma.sync.aligned.m16n8k16.row.col.f32.bf16.bf16.f32 "
        "{%0,%1,%2,%3}, {%4,%5,%6,%7}, {%8,%9}, {%0,%1,%2,%3};"
        : "+f"(c[0]), "+f"(c[1]), "+f"(c[2]), "+f"(c[3])
        : "r"(a[0]), "r"(a[1]), "r"(a[2]), "r"(a[3]), "r"(b0), "r"(b1));
}
__device__ __forceinline__ void cpasync16(uint32_t dst, const void* src) {
    asm volatile("cp.async.cg.shared.global [%0], [%1], 16;"
                 :: "r"(dst), "l"(src) : "memory");
}
#define CP_COMMIT() asm volatile("cp.async.commit_group;" ::: "memory")
#define CP_WAIT1()  asm volatile("cp.async.wait_group 1;" ::: "memory")
#define CP_WAIT0()  asm volatile("cp.async.wait_group 0;" ::: "memory")

// ---------------------------------------------------------------------------
// fp32 -> (bf16 hi, bf16 lo) split
// ---------------------------------------------------------------------------
__global__ void split_bf16(const float* __restrict__ x,
                           __nv_bfloat16* __restrict__ hi,
                           __nv_bfloat16* __restrict__ lo, int n4)
{
    int i = blockIdx.x * blockDim.x + threadIdx.x;
    if (i >= n4) return;
    float4 v = ((const float4*)x)[i];
    __nv_bfloat16 h0 = __float2bfloat16(v.x), h1 = __float2bfloat16(v.y);
    __nv_bfloat16 h2 = __float2bfloat16(v.z), h3 = __float2bfloat16(v.w);
    __nv_bfloat16 l0 = __float2bfloat16(v.x - __bfloat162float(h0));
    __nv_bfloat16 l1 = __float2bfloat16(v.y - __bfloat162float(h1));
    __nv_bfloat16 l2 = __float2bfloat16(v.z - __bfloat162float(h2));
    __nv_bfloat16 l3 = __float2bfloat16(v.w - __bfloat162float(h3));
    ((__nv_bfloat162*)hi)[2 * i]     = __halves2bfloat162(h0, h1);
    ((__nv_bfloat162*)hi)[2 * i + 1] = __halves2bfloat162(h2, h3);
    ((__nv_bfloat162*)lo)[2 * i]     = __halves2bfloat162(l0, l1);
    ((__nv_bfloat162*)lo)[2 * i + 1] = __halves2bfloat162(l2, l3);
}

// ---------------------------------------------------------------------------
// HMMA GEMM: C[M,N] = A[M,K] @ W[N,K]^T + bias, fp32-accurate via 3x bf16 mma.
// CTA 256 thr (8 warps 2x4), tile 128x128, K-chunk 32, cp.async double buffer.
// Smem stage (bf16 units, row stride 40): Ahi[128][40] Alo Bhi Blo.
// ---------------------------------------------------------------------------
#define GK        32
#define ROWSTRIDE 40                        /* bf16; 80 bytes */
#define SUBTILE_B (128 * ROWSTRIDE * 2)     /* 10240 bytes    */
#define STAGE_B   (4 * SUBTILE_B)           /* 40960 bytes    */
#define GEMM_SMEM (2 * STAGE_B)             /* 81920 bytes    */

struct GemmPtrs { const __nv_bfloat16 *ah, *al, *bh, *bl; };

__device__ __forceinline__ void load_stage(
    uint32_t sb, int tid, const GemmPtrs& p, int K, int k0)
{
    #pragma unroll
    for (int t = 0; t < 8; t++) {
        const int tile = t >> 1;
        const int rem  = ((t & 1) << 8) + tid;   // 0..511
        const int r    = rem >> 2;
        const int c8   = (rem & 3) << 3;
        const __nv_bfloat16* src =
            (tile == 0 ? p.ah : tile == 1 ? p.al : tile == 2 ? p.bh : p.bl)
            + (size_t)r * K + k0 + c8;
        uint32_t dst = sb + tile * SUBTILE_B + r * (ROWSTRIDE * 2) + c8 * 2;
        cpasync16(dst, src);
    }
}

__global__ __launch_bounds__(256, 1) void gemm_mma(
    const __nv_bfloat16* __restrict__ Ahi, const __nv_bfloat16* __restrict__ Alo,
    const __nv_bfloat16* __restrict__ Bhi, const __nv_bfloat16* __restrict__ Blo,
    const float* __restrict__ bias, float* __restrict__ C, int M, int N, int K)
{
    extern __shared__ char sm_[];
    const uint32_t smem_base = smem_u32(sm_);
    const int tid  = threadIdx.x;
    const int wid  = tid >> 5;
    const int lane = tid & 31;
    const int wm   = wid >> 2;          // 0..1
    const int wn   = wid & 3;           // 0..3
    const int brow = blockIdx.y << 7;
    const int bcol = blockIdx.x << 7;

    GemmPtrs p;
    p.ah = Ahi + (size_t)brow * K;  p.al = Alo + (size_t)brow * K;
    p.bh = Bhi + (size_t)bcol * K;  p.bl = Blo + (size_t)bcol * K;

    float acc[4][4][4];
    #pragma unroll
    for (int i = 0; i < 4; i++)
        #pragma unroll
        for (int j = 0; j < 4; j++)
            #pragma unroll
            for (int k = 0; k < 4; k++) acc[i][j][k] = 0.f;

    const int nchunks = K / GK;   // 128 or 32

    load_stage(smem_base, tid, p, K, 0);           CP_COMMIT();
    load_stage(smem_base + STAGE_B, tid, p, K, GK); CP_COMMIT();
    CP_WAIT1();
    __syncthreads();

    // ldmatrix lane addressing (canonical m16n8k16 row.col mapping)
    const int a_row = lane & 15;
    const int a_kb  = (lane >> 4) << 4;                     // 0 / 16 bytes
    const int b_row = (lane & 7) + ((lane >> 4) << 3);
    const int b_kb  = ((lane >> 3) & 1) << 4;

    for (int chunk = 0; chunk < nchunks; chunk++) {
        const uint32_t sb = smem_base + (chunk & 1) * STAGE_B;

        #pragma unroll
        for (int ks = 0; ks < 2; ks++) {
            uint32_t ah[4][4], al[4][4], bh[2][4], bl[2][4];
            #pragma unroll
            for (int mt = 0; mt < 4; mt++) {
                uint32_t ra = sb + (wm * 64 + mt * 16 + a_row) * (ROWSTRIDE * 2)
                            + ks * 32 + a_kb;
                ldsm4(ah[mt][0], ah[mt][1], ah[mt][2], ah[mt][3], ra);
                ldsm4(al[mt][0], al[mt][1], al[mt][2], al[mt][3], ra + SUBTILE_B);
            }
            #pragma unroll
            for (int bt = 0; bt < 2; bt++) {
                uint32_t rb = sb + 2 * SUBTILE_B
                            + (wn * 32 + bt * 16 + b_row) * (ROWSTRIDE * 2)
                            + ks * 32 + b_kb;
                ldsm4(bh[bt][0], bh[bt][1], bh[bt][2], bh[bt][3], rb);
                ldsm4(bl[bt][0], bl[bt][1], bl[bt][2], bl[bt][3], rb + SUBTILE_B);
            }
            #pragma unroll
            for (int mt = 0; mt < 4; mt++)
                #pragma unroll
                for (int bt = 0; bt < 2; bt++) {
                    mma16816(acc[mt][bt * 2],     ah[mt], bh[bt][0], bh[bt][1]);
                    mma16816(acc[mt][bt * 2 + 1], ah[mt], bh[bt][2], bh[bt][3]);
                    mma16816(acc[mt][bt * 2],     ah[mt], bl[bt][0], bl[bt][1]);
                    mma16816(acc[mt][bt * 2 + 1], ah[mt], bl[bt][2], bl[bt][3]);
                    mma16816(acc[mt][bt * 2],     al[mt], bh[bt][0], bh[bt][1]);
                    mma16816(acc[mt][bt * 2 + 1], al[mt], bh[bt][2], bh[bt][3]);
                }
        }
        __syncthreads();   // done reading this stage

        if (chunk + 2 < nchunks) {
            load_stage(smem_base + (chunk & 1) * STAGE_B, tid, p, K,
                       (chunk + 2) * GK);
            CP_COMMIT();
            CP_WAIT1();
            __syncthreads();
        } else if (chunk + 1 < nchunks) {
            CP_WAIT0();
            __syncthreads();
        }
    }

    // Epilogue: register frags -> global with bias (float2 stores)
    const int crow = lane >> 2;
    const int ccol = (lane & 3) << 1;
    #pragma unroll
    for (int nt = 0; nt < 4; nt++) {
        const int col = bcol + wn * 32 + nt * 8 + ccol;
        float b0 = __ldg(&bias[col]), b1 = __ldg(&bias[col + 1]);
        #pragma unroll
        for (int mt = 0; mt < 4; mt++) {
            size_t row0 = (size_t)(brow + wm * 64 + mt * 16 + crow);
            float2 v0 = { acc[mt][nt][0] + b0, acc[mt][nt][1] + b1 };
            float2 v1 = { acc[mt][nt][2] + b0, acc[mt][nt][3] + b1 };
            *(float2*)&C[row0 * N + col]       = v0;
            *(float2*)&C[(row0 + 8) * N + col] = v1;
        }
    }
}

// ---------------------------------------------------------------------------
// Causal GQA flash attention, fp32 (unchanged, known-good)
// ---------------------------------------------------------------------------
#define ATTN_LD 132
#define ATTN_SS 68
#define ATTN_SMEM ((2*64*ATTN_LD + 64*ATTN_SS) * (int)sizeof(float))

__global__ __launch_bounds__(256, 2) void attn_kernel(
    const float* __restrict__ Q, const float* __restrict__ K,
    const float* __restrict__ V, float* __restrict__ Y)
{
    extern __shared__ float sm[];
    float* Qs  = sm;
    float* KVs = sm + 64 * ATTN_LD;
    float* Ps  = sm + 2 * 64 * ATTN_LD;

    const int tid = threadIdx.x;
    const int ty  = tid >> 4;
    const int tx  = tid & 15;
    const int qt  = blockIdx.x;
    const int bh  = blockIdx.y;
    const int b   = bh >> 5;
    const int h   = bh & 31;
    const int g   = h >> 2;

    const float* Qbase = Q + ((size_t)(b * TT + qt * 64)) * DD + h * DH;
    const float* Kbase = K + (size_t)b * TT * KVD + g * DH;
    const float* Vbase = V + (size_t)b * TT * KVD + g * DH;

    for (int i = tid; i < 64 * 32; i += 256) {
        int r = i >> 5, c = (i & 31) << 2;
        *(float4*)&Qs[r * ATTN_LD + c] = *(const float4*)&Qbase[(size_t)r * DD + c];
    }

    float m_i[4], l_i[4], o[4][8];
    #pragma unroll
    for (int i = 0; i < 4; i++) {
        m_i[i] = -1e30f; l_i[i] = 0.f;
        #pragma unroll
        for (int j = 0; j < 8; j++) o[i][j] = 0.f;
    }
    __syncthreads();

    const float scale = 0.08838834764831843f;

    for (int kt = 0; kt <= qt; kt++) {
        for (int i = tid; i < 64 * 32; i += 256) {
            int r = i >> 5, c = (i & 31) << 2;
            *(float4*)&KVs[r * ATTN_LD + c] =
                *(const float4*)&Kbase[(size_t)(kt * 64 + r) * KVD + c];
        }
        __syncthreads();

        float s[4][4];
        #pragma unroll
        for (int i = 0; i < 4; i++)
            #pragma unroll
            for (int j = 0; j < 4; j++) s[i][j] = 0.f;

        #pragma unroll 8
        for (int k = 0; k < DH; k += 4) {
            float4 qv[4], kv[4];
            #pragma unroll
            for (int i = 0; i < 4; i++)
                qv[i] = *(const float4*)&Qs[(ty * 4 + i) * ATTN_LD + k];
            #pragma unroll
            for (int j = 0; j < 4; j++)
                kv[j] = *(const float4*)&KVs[(tx * 4 + j) * ATTN_LD + k];
            #pragma unroll
            for (int i = 0; i < 4; i++)
                #pragma unroll
                for (int j = 0; j < 4; j++) {
                    s[i][j] += qv[i].x * kv[j].x;
                    s[i][j] += qv[i].y * kv[j].y;
                    s[i][j] += qv[i].z * kv[j].z;
                    s[i][j] += qv[i].w * kv[j].w;
                }
        }

        const bool diag = (kt == qt);
        #pragma unroll
        for (int i = 0; i < 4; i++) {
            #pragma unroll
            for (int j = 0; j < 4; j++) {
                s[i][j] *= scale;
                if (diag && (tx * 4 + j) > (ty * 4 + i)) s[i][j] = -1e30f;
            }
            float v = fmaxf(fmaxf(s[i][0], s[i][1]), fmaxf(s[i][2], s[i][3]));
            #pragma unroll
            for (int off = 8; off; off >>= 1)
                v = fmaxf(v, __shfl_xor_sync(0xffffffffu, v, off));
            float mnew = fmaxf(m_i[i], v);
            float corr = __expf(m_i[i] - mnew);
            float ss = 0.f;
            #pragma unroll
            for (int j = 0; j < 4; j++) {
                s[i][j] = __expf(s[i][j] - mnew);
                ss += s[i][j];
            }
            #pragma unroll
            for (int off = 8; off; off >>= 1)
                ss += __shfl_xor_sync(0xffffffffu, ss, off);
            l_i[i] = l_i[i] * corr + ss;
            m_i[i] = mnew;
            #pragma unroll
            for (int j = 0; j < 8; j++) o[i][j] *= corr;
            #pragma unroll
            for (int j = 0; j < 4; j++)
                Ps[(ty * 4 + i) * ATTN_SS + tx * 4 + j] = s[i][j];
        }
        __syncthreads();

        for (int i = tid; i < 64 * 32; i += 256) {
            int r = i >> 5, c = (i & 31) << 2;
            *(float4*)&KVs[r * ATTN_LD + c] =
                *(const float4*)&Vbase[(size_t)(kt * 64 + r) * KVD + c];
        }
        __syncthreads();

        #pragma unroll 4
        for (int s2 = 0; s2 < 64; s2++) {
            float pv[4];
            #pragma unroll
            for (int i = 0; i < 4; i++) pv[i] = Ps[(ty * 4 + i) * ATTN_SS + s2];
            float vv[8];
            #pragma unroll
            for (int j = 0; j < 8; j++) vv[j] = KVs[s2 * ATTN_LD + tx + j * 16];
            #pragma unroll
            for (int i = 0; i < 4; i++)
                #pragma unroll
                for (int j = 0; j < 8; j++) o[i][j] += pv[i] * vv[j];
        }
        __syncthreads();
    }

    #pragma unroll
    for (int i = 0; i < 4; i++) {
        float inv = 1.f / l_i[i];
        size_t row = (size_t)(b * TT + qt * 64 + ty * 4 + i);
        #pragma unroll
        for (int j = 0; j < 8; j++)
            Y[row * DD + h * DH + tx + j * 16] = o[i][j] * inv;
    }
}

// ---------------------------------------------------------------------------
extern "C" void kernel_launch(void* const* d_in, const int* in_sizes, int n_in,
                              void* d_out, int out_size)
{
    (void)in_sizes; (void)n_in; (void)out_size;
    const float* X  = (const float*)d_in[0];
    const float* Wq = (const float*)d_in[1];
    const float* bq = (const float*)d_in[2];
    const float* Wk = (const float*)d_in[3];
    const float* bk = (const float*)d_in[4];
    const float* Wv = (const float*)d_in[5];
    const float* bv = (const float*)d_in[6];
    const float* Wo = (const float*)d_in[7];
    const float* bo = (const float*)d_in[8];
    float* out = (float*)d_out;

    float *Qp, *Kp, *Vp, *Yp;
    cudaGetSymbolAddress((void**)&Qp, g_Q);
    cudaGetSymbolAddress((void**)&Kp, g_K);
    cudaGetSymbolAddress((void**)&Vp, g_V);
    cudaGetSymbolAddress((void**)&Yp, g_Y);
    __nv_bfloat16 *Xh, *Xl, *Wqh, *Wql, *Wkh, *Wkl, *Wvh, *Wvl, *Woh, *Wol, *Yh, *Yl;
    cudaGetSymbolAddress((void**)&Xh, g_X_hi);   cudaGetSymbolAddress((void**)&Xl, g_X_lo);
    cudaGetSymbolAddress((void**)&Wqh, g_Wq_hi); cudaGetSymbolAddress((void**)&Wql, g_Wq_lo);
    cudaGetSymbolAddress((void**)&Wkh, g_Wk_hi); cudaGetSymbolAddress((void**)&Wkl, g_Wk_lo);
    cudaGetSymbolAddress((void**)&Wvh, g_Wv_hi); cudaGetSymbolAddress((void**)&Wvl, g_Wv_lo);
    cudaGetSymbolAddress((void**)&Woh, g_Wo_hi); cudaGetSymbolAddress((void**)&Wol, g_Wo_lo);
    cudaGetSymbolAddress((void**)&Yh, g_Y_hi);   cudaGetSymbolAddress((void**)&Yl, g_Y_lo);

    cudaFuncSetAttribute(attn_kernel,
                         cudaFuncAttributeMaxDynamicSharedMemorySize, ATTN_SMEM);
    cudaFuncSetAttribute(gemm_mma,
                         cudaFuncAttributeMaxDynamicSharedMemorySize, GEMM_SMEM);

    const int nXD = MTOT * DD / 4, nDD = DD * DD / 4, nKD = KVD * DD / 4;
    split_bf16<<<(nXD + 255) / 256, 256>>>(X,  Xh,  Xl,  nXD);
    split_bf16<<<(nDD + 255) / 256, 256>>>(Wq, Wqh, Wql, nDD);
    split_bf16<<<(nKD + 255) / 256, 256>>>(Wk, Wkh, Wkl, nKD);
    split_bf16<<<(nKD + 255) / 256, 256>>>(Wv, Wvh, Wvl, nKD);
    split_bf16<<<(nDD + 255) / 256, 256>>>(Wo, Woh, Wol, nDD);

    gemm_mma<<<dim3(DD / 128,  MTOT / 128), 256, GEMM_SMEM>>>(Xh, Xl, Wqh, Wql, bq, Qp, MTOT, DD,  DD);
    gemm_mma<<<dim3(KVD / 128, MTOT / 128), 256, GEMM_SMEM>>>(Xh, Xl, Wkh, Wkl, bk, Kp, MTOT, KVD, DD);
    gemm_mma<<<dim3(KVD / 128, MTOT / 128), 256, GEMM_SMEM>>>(Xh, Xl, Wvh, Wvl, bv, Vp, MTOT, KVD, DD);

    attn_kernel<<<dim3(TT / 64, BB * HH), 256, ATTN_SMEM>>>(Qp, Kp, Vp, Yp);

    split_bf16<<<(nXD + 255) / 256, 256>>>(Yp, Yh, Yl, nXD);
    gemm_mma<<<dim3(DD / 128, MTOT / 128), 256, GEMM_SMEM>>>(Yh, Yl, Woh, Wol, bo, out, MTOT, DD, DD);
}

// round 5
// speedup vs baseline: 3.1316x; 1.7257x over previous
#include <cuda_runtime.h>
#include <cuda_bf16.h>
#include <cstdint>

#define BB   2
#define TT   2048
#define DD   4096
#define HH   32
#define GG   8
#define DH   128
#define KVD  (GG*DH)     /* 1024 */
#define MTOT (BB*TT)     /* 4096 */

// bf16 hi/lo split operands (device globals — no runtime allocation)
__device__ __nv_bfloat16 g_X_hi[(size_t)MTOT * DD], g_X_lo[(size_t)MTOT * DD];
__device__ __nv_bfloat16 g_Wq_hi[(size_t)DD * DD],  g_Wq_lo[(size_t)DD * DD];
__device__ __nv_bfloat16 g_Wk_hi[(size_t)KVD * DD], g_Wk_lo[(size_t)KVD * DD];
__device__ __nv_bfloat16 g_Wv_hi[(size_t)KVD * DD], g_Wv_lo[(size_t)KVD * DD];
__device__ __nv_bfloat16 g_Wo_hi[(size_t)DD * DD],  g_Wo_lo[(size_t)DD * DD];
__device__ __nv_bfloat16 g_Q_hi[(size_t)MTOT * DD],  g_Q_lo[(size_t)MTOT * DD];
__device__ __nv_bfloat16 g_K_hi[(size_t)MTOT * KVD], g_K_lo[(size_t)MTOT * KVD];
__device__ __nv_bfloat16 g_V_hi[(size_t)MTOT * KVD], g_V_lo[(size_t)MTOT * KVD];
__device__ __nv_bfloat16 g_Y_hi[(size_t)MTOT * DD],  g_Y_lo[(size_t)MTOT * DD];

// ---------------------------------------------------------------------------
// base-PTX helpers (compute_103-safe)
// ---------------------------------------------------------------------------
__device__ __forceinline__ uint32_t smem_u32(const void* p) {
    uint32_t a;
    asm("{ .reg .u64 t; cvta.to.shared.u64 t, %1; cvt.u32.u64 %0, t; }"
        : "=r"(a) : "l"(p));
    return a;
}
__device__ __forceinline__ void ldsm4(uint32_t& r0, uint32_t& r1, uint32_t& r2,
                                      uint32_t& r3, uint32_t addr) {
    asm volatile("ldmatrix.sync.aligned.m8n8.x4.shared.b16 {%0,%1,%2,%3}, [%4];"
                 : "=r"(r0), "=r"(r1), "=r"(r2), "=r"(r3) : "r"(addr));
}
__device__ __forceinline__ void ldsm4t(uint32_t& r0, uint32_t& r1, uint32_t& r2,
                                       uint32_t& r3, uint32_t addr) {
    asm volatile("ldmatrix.sync.aligned.m8n8.x4.trans.shared.b16 {%0,%1,%2,%3}, [%4];"
                 : "=r"(r0), "=r"(r1), "=r"(r2), "=r"(r3) : "r"(addr));
}
__device__ __forceinline__ void mma16816(float* c, const uint32_t* a,
                                         uint32_t b0, uint32_t b1) {
    asm volatile(
        "mma.sync.aligned.m16n8k16.row.col.f32.bf16.bf16.f32 "
        "{%0,%1,%2,%3}, {%4,%5,%6,%7}, {%8,%9}, {%0,%1,%2,%3};"
        : "+f"(c[0]), "+f"(c[1]), "+f"(c[2]), "+f"(c[3])
        : "r"(a[0]), "r"(a[1]), "r"(a[2]), "r"(a[3]), "r"(b0), "r"(b1));
}
__device__ __forceinline__ void cpasync16(uint32_t dst, const void* src) {
    asm volatile("cp.async.cg.shared.global [%0], [%1], 16;"
                 :: "r"(dst), "l"(src) : "memory");
}
#define CP_COMMIT() asm volatile("cp.async.commit_group;" ::: "memory")
#define CP_WAIT1()  asm volatile("cp.async.wait_group 1;" ::: "memory")
#define CP_WAIT0()  asm volatile("cp.async.wait_group 0;" ::: "memory")

__device__ __forceinline__ float ex2f(float x) {
    float y;
    asm("ex2.approx.ftz.f32 %0, %1;" : "=f"(y) : "f"(x));
    return y;
}
// split pair (a,b) -> hi bf16x2 + residual bf16x2 (lo halves = a)
__device__ __forceinline__ void split_pack(float a, float b,
                                           uint32_t& h, uint32_t& l) {
    __nv_bfloat162 hb = __floats2bfloat162_rn(a, b);
    __nv_bfloat162 lb = __floats2bfloat162_rn(a - __low2float(hb),
                                              b - __high2float(hb));
    h = *reinterpret_cast<uint32_t*>(&hb);
    l = *reinterpret_cast<uint32_t*>(&lb);
}

// ---------------------------------------------------------------------------
// fp32 -> (bf16 hi, bf16 lo) split
// ---------------------------------------------------------------------------
__global__ void split_bf16(const float* __restrict__ x,
                           __nv_bfloat16* __restrict__ hi,
                           __nv_bfloat16* __restrict__ lo, int n4)
{
    int i = blockIdx.x * blockDim.x + threadIdx.x;
    if (i >= n4) return;
    float4 v = ((const float4*)x)[i];
    uint32_t h0, l0, h1, l1;
    split_pack(v.x, v.y, h0, l0);
    split_pack(v.z, v.w, h1, l1);
    ((uint32_t*)hi)[2 * i] = h0; ((uint32_t*)hi)[2 * i + 1] = h1;
    ((uint32_t*)lo)[2 * i] = l0; ((uint32_t*)lo)[2 * i + 1] = l1;
}

// ---------------------------------------------------------------------------
// HMMA GEMM: C = A @ W^T + bias via 3x bf16 mma; optional split bf16 output.
// ---------------------------------------------------------------------------
#define GK        32
#define ROWSTRIDE 40
#define SUBTILE_B (128 * ROWSTRIDE * 2)
#define STAGE_B   (4 * SUBTILE_B)
#define GEMM_SMEM (2 * STAGE_B)

struct GemmPtrs { const __nv_bfloat16 *ah, *al, *bh, *bl; };

__device__ __forceinline__ void load_stage(
    uint32_t sb, int tid, const GemmPtrs& p, int K, int k0)
{
    #pragma unroll
    for (int t = 0; t < 8; t++) {
        const int tile = t >> 1;
        const int rem  = ((t & 1) << 8) + tid;
        const int r    = rem >> 2;
        const int c8   = (rem & 3) << 3;
        const __nv_bfloat16* src =
            (tile == 0 ? p.ah : tile == 1 ? p.al : tile == 2 ? p.bh : p.bl)
            + (size_t)r * K + k0 + c8;
        cpasync16(sb + tile * SUBTILE_B + r * (ROWSTRIDE * 2) + c8 * 2, src);
    }
}

__global__ __launch_bounds__(256, 1) void gemm_mma(
    const __nv_bfloat16* __restrict__ Ahi, const __nv_bfloat16* __restrict__ Alo,
    const __nv_bfloat16* __restrict__ Bhi, const __nv_bfloat16* __restrict__ Blo,
    const float* __restrict__ bias,
    float* __restrict__ Cf,                       // fp32 out (or null)
    __nv_bfloat16* __restrict__ Ch, __nv_bfloat16* __restrict__ Cl,
    int M, int N, int K)
{
    extern __shared__ char sm_[];
    const uint32_t smem_base = smem_u32(sm_);
    const int tid  = threadIdx.x;
    const int wid  = tid >> 5;
    const int lane = tid & 31;
    const int wm   = wid >> 2;
    const int wn   = wid & 3;
    const int brow = blockIdx.y << 7;
    const int bcol = blockIdx.x << 7;

    GemmPtrs p;
    p.ah = Ahi + (size_t)brow * K;  p.al = Alo + (size_t)brow * K;
    p.bh = Bhi + (size_t)bcol * K;  p.bl = Blo + (size_t)bcol * K;

    float acc[4][4][4];
    #pragma unroll
    for (int i = 0; i < 4; i++)
        #pragma unroll
        for (int j = 0; j < 4; j++)
            #pragma unroll
            for (int k = 0; k < 4; k++) acc[i][j][k] = 0.f;

    const int nchunks = K / GK;

    load_stage(smem_base, tid, p, K, 0);            CP_COMMIT();
    load_stage(smem_base + STAGE_B, tid, p, K, GK); CP_COMMIT();
    CP_WAIT1();
    __syncthreads();

    const int a_row = lane & 15;
    const int a_kb  = (lane >> 4) << 4;
    const int b_row = (lane & 7) + ((lane >> 4) << 3);
    const int b_kb  = ((lane >> 3) & 1) << 4;

    for (int chunk = 0; chunk < nchunks; chunk++) {
        const uint32_t sb = smem_base + (chunk & 1) * STAGE_B;

        #pragma unroll
        for (int ks = 0; ks < 2; ks++) {
            uint32_t ah[4][4], al[4][4], bh[2][4], bl[2][4];
            #pragma unroll
            for (int mt = 0; mt < 4; mt++) {
                uint32_t ra = sb + (wm * 64 + mt * 16 + a_row) * (ROWSTRIDE * 2)
                            + ks * 32 + a_kb;
                ldsm4(ah[mt][0], ah[mt][1], ah[mt][2], ah[mt][3], ra);
                ldsm4(al[mt][0], al[mt][1], al[mt][2], al[mt][3], ra + SUBTILE_B);
            }
            #pragma unroll
            for (int bt = 0; bt < 2; bt++) {
                uint32_t rb = sb + 2 * SUBTILE_B
                            + (wn * 32 + bt * 16 + b_row) * (ROWSTRIDE * 2)
                            + ks * 32 + b_kb;
                ldsm4(bh[bt][0], bh[bt][1], bh[bt][2], bh[bt][3], rb);
                ldsm4(bl[bt][0], bl[bt][1], bl[bt][2], bl[bt][3], rb + SUBTILE_B);
            }
            #pragma unroll
            for (int mt = 0; mt < 4; mt++)
                #pragma unroll
                for (int bt = 0; bt < 2; bt++) {
                    mma16816(acc[mt][bt * 2],     ah[mt], bh[bt][0], bh[bt][1]);
                    mma16816(acc[mt][bt * 2 + 1], ah[mt], bh[bt][2], bh[bt][3]);
                    mma16816(acc[mt][bt * 2],     ah[mt], bl[bt][0], bl[bt][1]);
                    mma16816(acc[mt][bt * 2 + 1], ah[mt], bl[bt][2], bl[bt][3]);
                    mma16816(acc[mt][bt * 2],     al[mt], bh[bt][0], bh[bt][1]);
                    mma16816(acc[mt][bt * 2 + 1], al[mt], bh[bt][2], bh[bt][3]);
                }
        }
        __syncthreads();

        if (chunk + 2 < nchunks) {
            load_stage(smem_base + (chunk & 1) * STAGE_B, tid, p, K,
                       (chunk + 2) * GK);
            CP_COMMIT();
            CP_WAIT1();
            __syncthreads();
        } else if (chunk + 1 < nchunks) {
            CP_WAIT0();
            __syncthreads();
        }
    }

    const int crow = lane >> 2;
    const int ccol = (lane & 3) << 1;
    #pragma unroll
    for (int nt = 0; nt < 4; nt++) {
        const int col = bcol + wn * 32 + nt * 8 + ccol;
        float b0 = __ldg(&bias[col]), b1 = __ldg(&bias[col + 1]);
        #pragma unroll
        for (int mt = 0; mt < 4; mt++) {
            size_t row0 = (size_t)(brow + wm * 64 + mt * 16 + crow);
            float x0 = acc[mt][nt][0] + b0, x1 = acc[mt][nt][1] + b1;
            float x2 = acc[mt][nt][2] + b0, x3 = acc[mt][nt][3] + b1;
            if (Cf) {
                float2 v0 = { x0, x1 }, v1 = { x2, x3 };
                *(float2*)&Cf[row0 * N + col]       = v0;
                *(float2*)&Cf[(row0 + 8) * N + col] = v1;
            } else {
                uint32_t h0, l0, h1, l1;
                split_pack(x0, x1, h0, l0);
                split_pack(x2, x3, h1, l1);
                *(uint32_t*)&Ch[row0 * N + col]       = h0;
                *(uint32_t*)&Cl[row0 * N + col]       = l0;
                *(uint32_t*)&Ch[(row0 + 8) * N + col] = h1;
                *(uint32_t*)&Cl[(row0 + 8) * N + col] = l1;
            }
        }
    }
}

// ---------------------------------------------------------------------------
// HMMA causal GQA flash attention (3-term bf16 for QK^T and P*V).
// CTA 256 thr (8 warps x 16 q-rows = 128 q-rows), k-tile 64, double-buffered
// K/V via cp.async. SMEM rows 272B (17 x 16B groups -> ldmatrix conflict-free).
// ---------------------------------------------------------------------------
#define ATSTR 272                       /* bytes per 128-col bf16 row */
#define AT64  (64 * ATSTR)              /* 17408: one 64-row tile     */
#define AQ_B  (128 * ATSTR)             /* 34816: Q tile (128 rows)   */
#define AKV_B (4 * AT64)                /* Kh,Kl,Vh,Vl per buffer     */
#define ATTN_SMEM (2 * AQ_B + 2 * AKV_B)  /* 208896 */

__device__ __forceinline__ void attn_load_kv(
    uint32_t base, int tid,
    const __nv_bfloat16* __restrict__ Kh, const __nv_bfloat16* __restrict__ Kl,
    const __nv_bfloat16* __restrict__ Vh, const __nv_bfloat16* __restrict__ Vl,
    size_t grow0, int gcol)
{
    const __nv_bfloat16* srcs[4] = { Kh, Kl, Vh, Vl };
    #pragma unroll
    for (int t = 0; t < 4; t++) {
        const __nv_bfloat16* s = srcs[t] + grow0 * KVD + gcol;
        #pragma unroll
        for (int i = 0; i < 4; i++) {
            int ch = tid + i * 256;           // 0..1023
            int r = ch >> 4, c = ch & 15;
            cpasync16(base + t * AT64 + r * ATSTR + c * 16,
                      s + (size_t)r * KVD + c * 8);
        }
    }
    CP_COMMIT();
}

__global__ __launch_bounds__(256, 1) void attn_mma(
    const __nv_bfloat16* __restrict__ Qh_, const __nv_bfloat16* __restrict__ Ql_,
    const __nv_bfloat16* __restrict__ Kh_, const __nv_bfloat16* __restrict__ Kl_,
    const __nv_bfloat16* __restrict__ Vh_, const __nv_bfloat16* __restrict__ Vl_,
    __nv_bfloat16* __restrict__ Yh_, __nv_bfloat16* __restrict__ Yl_)
{
    extern __shared__ char sm_[];
    const uint32_t sb = smem_u32(sm_);
    const int tid  = threadIdx.x;
    const int lane = tid & 31;
    const int w    = tid >> 5;
    const int qt   = (int)gridDim.x - 1 - (int)blockIdx.x;  // heavy tiles first
    const int bh   = blockIdx.y;
    const int b    = bh >> 5, h = bh & 31, g = h >> 2;
    const int ktmax = 2 * qt + 1;
    const size_t qrow0 = (size_t)b * TT + (size_t)qt * 128;
    const size_t krow0 = (size_t)b * TT;
    const int gcol = g * DH;

    // Q tiles (hi & lo) via cp.async
    {
        const __nv_bfloat16* q0 = Qh_ + qrow0 * DD + h * DH;
        const __nv_bfloat16* q1 = Ql_ + qrow0 * DD + h * DH;
        #pragma unroll
        for (int i = 0; i < 8; i++) {
            int ch = tid + i * 256;           // 0..2047
            int r = ch >> 4, c = ch & 15;
            cpasync16(sb + r * ATSTR + c * 16,        q0 + (size_t)r * DD + c * 8);
            cpasync16(sb + AQ_B + r * ATSTR + c * 16, q1 + (size_t)r * DD + c * 8);
        }
        CP_COMMIT();
    }
    attn_load_kv(sb + 2 * AQ_B, tid, Kh_, Kl_, Vh_, Vl_, krow0, gcol);
    attn_load_kv(sb + 2 * AQ_B + AKV_B, tid, Kh_, Kl_, Vh_, Vl_, krow0 + 64, gcol);

    float o[16][4];
    #pragma unroll
    for (int i = 0; i < 16; i++)
        #pragma unroll
        for (int j = 0; j < 4; j++) o[i][j] = 0.f;
    float m_lo = -1e30f, m_hi = -1e30f, l_lo = 0.f, l_hi = 0.f;

    const int wrow = qt * 128 + w * 16;       // seq-local warp row base
    const int rl   = lane >> 2;
    const float SC = 0.088388347648318447f * 1.4426950408889634f; // scale*log2e

    for (int kt = 0; kt <= ktmax; kt++) {
        if (kt < ktmax) { CP_WAIT1(); } else { CP_WAIT0(); }
        __syncthreads();
        const uint32_t kb = sb + 2 * AQ_B + (kt & 1) * AKV_B;

        if (kt * 64 <= wrow + 15) {           // warp has visible keys
            float s[8][4];
            #pragma unroll
            for (int j = 0; j < 8; j++)
                #pragma unroll
                for (int e = 0; e < 4; e++) s[j][e] = 0.f;

            // ---- S = Q K^T ----
            #pragma unroll
            for (int ks = 0; ks < 8; ks++) {
                uint32_t qh[4], ql[4];
                uint32_t ra = sb + (w * 16 + (lane & 15)) * ATSTR
                            + ks * 32 + ((lane >> 4) << 4);
                ldsm4(qh[0], qh[1], qh[2], qh[3], ra);
                ldsm4(ql[0], ql[1], ql[2], ql[3], ra + AQ_B);
                #pragma unroll
                for (int np = 0; np < 4; np++) {
                    uint32_t kh[4], kl[4];
                    uint32_t rb = kb
                        + (np * 16 + (lane & 7) + ((lane >> 4) << 3)) * ATSTR
                        + ks * 32 + (((lane >> 3) & 1) << 4);
                    ldsm4(kh[0], kh[1], kh[2], kh[3], rb);
                    ldsm4(kl[0], kl[1], kl[2], kl[3], rb + AT64);
                    mma16816(s[2 * np],     qh, kh[0], kh[1]);
                    mma16816(s[2 * np],     qh, kl[0], kl[1]);
                    mma16816(s[2 * np],     ql, kh[0], kh[1]);
                    mma16816(s[2 * np + 1], qh, kh[2], kh[3]);
                    mma16816(s[2 * np + 1], qh, kl[2], kl[3]);
                    mma16816(s[2 * np + 1], ql, kh[2], kh[3]);
                }
            }

            // ---- scale (log2 units) + causal mask ----
            #pragma unroll
            for (int j = 0; j < 8; j++)
                #pragma unroll
                for (int e = 0; e < 4; e++) s[j][e] *= SC;
            if (kt * 64 + 63 > wrow) {
                const int row_lo = wrow + rl, row_hi = row_lo + 8;
                #pragma unroll
                for (int j = 0; j < 8; j++) {
                    int c0 = kt * 64 + j * 8 + ((lane & 3) << 1);
                    if (c0 > row_lo)     s[j][0] = -1e30f;
                    if (c0 + 1 > row_lo) s[j][1] = -1e30f;
                    if (c0 > row_hi)     s[j][2] = -1e30f;
                    if (c0 + 1 > row_hi) s[j][3] = -1e30f;
                }
            }

            // ---- online softmax ----
            float mx0 = -1e30f, mx1 = -1e30f;
            #pragma unroll
            for (int j = 0; j < 8; j++) {
                mx0 = fmaxf(mx0, fmaxf(s[j][0], s[j][1]));
                mx1 = fmaxf(mx1, fmaxf(s[j][2], s[j][3]));
            }
            mx0 = fmaxf(mx0, __shfl_xor_sync(0xffffffffu, mx0, 1));
            mx0 = fmaxf(mx0, __shfl_xor_sync(0xffffffffu, mx0, 2));
            mx1 = fmaxf(mx1, __shfl_xor_sync(0xffffffffu, mx1, 1));
            mx1 = fmaxf(mx1, __shfl_xor_sync(0xffffffffu, mx1, 2));
            float mn0 = fmaxf(m_lo, mx0), mn1 = fmaxf(m_hi, mx1);
            float c0 = ex2f(m_lo - mn0), c1 = ex2f(m_hi - mn1);
            float su0 = 0.f, su1 = 0.f;
            #pragma unroll
            for (int j = 0; j < 8; j++) {
                s[j][0] = ex2f(s[j][0] - mn0);
                s[j][1] = ex2f(s[j][1] - mn0);
                s[j][2] = ex2f(s[j][2] - mn1);
                s[j][3] = ex2f(s[j][3] - mn1);
                su0 += s[j][0] + s[j][1];
                su1 += s[j][2] + s[j][3];
            }
            su0 += __shfl_xor_sync(0xffffffffu, su0, 1);
            su0 += __shfl_xor_sync(0xffffffffu, su0, 2);
            su1 += __shfl_xor_sync(0xffffffffu, su1, 1);
            su1 += __shfl_xor_sync(0xffffffffu, su1, 2);
            l_lo = l_lo * c0 + su0;  l_hi = l_hi * c1 + su1;
            m_lo = mn0;              m_hi = mn1;
            #pragma unroll
            for (int nt = 0; nt < 16; nt++) {
                o[nt][0] *= c0; o[nt][1] *= c0;
                o[nt][2] *= c1; o[nt][3] *= c1;
            }

            // ---- O += P V ----
            #pragma unroll
            for (int ks = 0; ks < 4; ks++) {
                uint32_t ph[4], pl[4];
                split_pack(s[2 * ks][0],     s[2 * ks][1],     ph[0], pl[0]);
                split_pack(s[2 * ks][2],     s[2 * ks][3],     ph[1], pl[1]);
                split_pack(s[2 * ks + 1][0], s[2 * ks + 1][1], ph[2], pl[2]);
                split_pack(s[2 * ks + 1][2], s[2 * ks + 1][3], ph[3], pl[3]);
                #pragma unroll
                for (int np = 0; np < 8; np++) {
                    uint32_t vh[4], vl[4];
                    uint32_t rv = kb + 2 * AT64
                        + (ks * 16 + (lane & 15)) * ATSTR
                        + np * 32 + ((lane >> 4) << 4);
                    ldsm4t(vh[0], vh[1], vh[2], vh[3], rv);
                    ldsm4t(vl[0], vl[1], vl[2], vl[3], rv + AT64);
                    mma16816(o[2 * np],     ph, vh[0], vh[1]);
                    mma16816(o[2 * np],     ph, vl[0], vl[1]);
                    mma16816(o[2 * np],     pl, vh[0], vh[1]);
                    mma16816(o[2 * np + 1], ph, vh[2], vh[3]);
                    mma16816(o[2 * np + 1], ph, vl[2], vl[3]);
                    mma16816(o[2 * np + 1], pl, vh[2], vh[3]);
                }
            }
        }
        __syncthreads();
        if (kt + 2 <= ktmax)
            attn_load_kv(sb + 2 * AQ_B + (kt & 1) * AKV_B, tid,
                         Kh_, Kl_, Vh_, Vl_, krow0 + (size_t)(kt + 2) * 64, gcol);
    }

    // ---- epilogue: normalize, split to bf16 hi/lo, store ----
    const float i0 = 1.f / l_lo, i1 = 1.f / l_hi;
    const size_t row_lo = qrow0 + w * 16 + rl;
    const size_t row_hi = row_lo + 8;
    const int colb = h * DH + ((lane & 3) << 1);
    #pragma unroll
    for (int nt = 0; nt < 16; nt++) {
        int col = colb + nt * 8;
        uint32_t h0, l0, h1, l1;
        split_pack(o[nt][0] * i0, o[nt][1] * i0, h0, l0);
        split_pack(o[nt][2] * i1, o[nt][3] * i1, h1, l1);
        *(uint32_t*)&Yh_[row_lo * DD + col] = h0;
        *(uint32_t*)&Yl_[row_lo * DD + col] = l0;
        *(uint32_t*)&Yh_[row_hi * DD + col] = h1;
        *(uint32_t*)&Yl_[row_hi * DD + col] = l1;
    }
}

// ---------------------------------------------------------------------------
extern "C" void kernel_launch(void* const* d_in, const int* in_sizes, int n_in,
                              void* d_out, int out_size)
{
    (void)in_sizes; (void)n_in; (void)out_size;
    const float* X  = (const float*)d_in[0];
    const float* Wq = (const float*)d_in[1];
    const float* bq = (const float*)d_in[2];
    const float* Wk = (const float*)d_in[3];
    const float* bk = (const float*)d_in[4];
    const float* Wv = (const float*)d_in[5];
    const float* bv = (const float*)d_in[6];
    const float* Wo = (const float*)d_in[7];
    const float* bo = (const float*)d_in[8];
    float* out = (float*)d_out;

    __nv_bfloat16 *Xh, *Xl, *Wqh, *Wql, *Wkh, *Wkl, *Wvh, *Wvl, *Woh, *Wol;
    __nv_bfloat16 *Qh, *Ql, *Kh, *Kl, *Vh, *Vl, *Yh, *Yl;
    cudaGetSymbolAddress((void**)&Xh, g_X_hi);   cudaGetSymbolAddress((void**)&Xl, g_X_lo);
    cudaGetSymbolAddress((void**)&Wqh, g_Wq_hi); cudaGetSymbolAddress((void**)&Wql, g_Wq_lo);
    cudaGetSymbolAddress((void**)&Wkh, g_Wk_hi); cudaGetSymbolAddress((void**)&Wkl, g_Wk_lo);
    cudaGetSymbolAddress((void**)&Wvh, g_Wv_hi); cudaGetSymbolAddress((void**)&Wvl, g_Wv_lo);
    cudaGetSymbolAddress((void**)&Woh, g_Wo_hi); cudaGetSymbolAddress((void**)&Wol, g_Wo_lo);
    cudaGetSymbolAddress((void**)&Qh, g_Q_hi);   cudaGetSymbolAddress((void**)&Ql, g_Q_lo);
    cudaGetSymbolAddress((void**)&Kh, g_K_hi);   cudaGetSymbolAddress((void**)&Kl, g_K_lo);
    cudaGetSymbolAddress((void**)&Vh, g_V_hi);   cudaGetSymbolAddress((void**)&Vl, g_V_lo);
    cudaGetSymbolAddress((void**)&Yh, g_Y_hi);   cudaGetSymbolAddress((void**)&Yl, g_Y_lo);

    cudaFuncSetAttribute(gemm_mma,
                         cudaFuncAttributeMaxDynamicSharedMemorySize, GEMM_SMEM);
    cudaFuncSetAttribute(attn_mma,
                         cudaFuncAttributeMaxDynamicSharedMemorySize, ATTN_SMEM);

    const int nXD = MTOT * DD / 4, nDD = DD * DD / 4, nKD = KVD * DD / 4;
    split_bf16<<<(nXD + 255) / 256, 256>>>(X,  Xh,  Xl,  nXD);
    split_bf16<<<(nDD + 255) / 256, 256>>>(Wq, Wqh, Wql, nDD);
    split_bf16<<<(nKD + 255) / 256, 256>>>(Wk, Wkh, Wkl, nKD);
    split_bf16<<<(nKD + 255) / 256, 256>>>(Wv, Wvh, Wvl, nKD);
    split_bf16<<<(nDD + 255) / 256, 256>>>(Wo, Woh, Wol, nDD);

    // QKV projections -> bf16 hi/lo directly
    gemm_mma<<<dim3(DD / 128,  MTOT / 128), 256, GEMM_SMEM>>>(
        Xh, Xl, Wqh, Wql, bq, nullptr, Qh, Ql, MTOT, DD,  DD);
    gemm_mma<<<dim3(KVD / 128, MTOT / 128), 256, GEMM_SMEM>>>(
        Xh, Xl, Wkh, Wkl, bk, nullptr, Kh, Kl, MTOT, KVD, DD);
    gemm_mma<<<dim3(KVD / 128, MTOT / 128), 256, GEMM_SMEM>>>(
        Xh, Xl, Wvh, Wvl, bv, nullptr, Vh, Vl, MTOT, KVD, DD);

    // causal GQA attention on tensor cores -> Y hi/lo
    attn_mma<<<dim3(TT / 128, BB * HH), 256, ATTN_SMEM>>>(
        Qh, Ql, Kh, Kl, Vh, Vl, Yh, Yl);

    // output projection -> fp32
    gemm_mma<<<dim3(DD / 128, MTOT / 128), 256, GEMM_SMEM>>>(
        Yh, Yl, Woh, Wol, bo, out, nullptr, nullptr, MTOT, DD, DD);
}